// round 11
// baseline (speedup 1.0000x reference)
#include <cuda_runtime.h>
#include <cuda_bf16.h>
#include <cstdint>

#define SHIFT 4
#define NR 225
#define TSU 18            // embed table row stride in u32 (36 bf16)
#define VTS 68            // V^T row stride in u32 (136 bf16)
#define SCALE 0.17677669529663687f

// smem byte offsets
#define QH_B   0          // bf16 q hi, token-major, 20 u32/row (10240)
#define QL_B   10240
#define KH_B   20480
#define KL_B   30720
#define KEB_B  40960      // bf16 k_embed 225x36  (16200)
#define QEB_B  57160      // bf16 q_embed 225x36
#define VEB_B  73360      // bf16 v_embed 225x36
#define VTH_B  89560      // bf16 V^T hi 32x136   (8704)
#define VTL_B  98264
#define SMEM_BYTES 107008

__device__ __forceinline__ void mma_bf16(float* d, uint32_t a0, uint32_t a1, uint32_t a2, uint32_t a3,
                                         uint32_t b0, uint32_t b1) {
    asm volatile(
        "mma.sync.aligned.m16n8k16.row.col.f32.bf16.bf16.f32 "
        "{%0,%1,%2,%3},{%4,%5,%6,%7},{%8,%9},{%0,%1,%2,%3};"
        : "+f"(d[0]), "+f"(d[1]), "+f"(d[2]), "+f"(d[3])
        : "r"(a0), "r"(a1), "r"(a2), "r"(a3), "r"(b0), "r"(b1));
}
__device__ __forceinline__ uint32_t pkhi(float a, float b) {
    __nv_bfloat162 t = __floats2bfloat162_rn(a, b);
    return *reinterpret_cast<uint32_t*>(&t);
}
__device__ __forceinline__ uint32_t pklo(float a, float b) {
    float ha = __bfloat162float(__float2bfloat16(a));
    float hb = __bfloat162float(__float2bfloat16(b));
    __nv_bfloat162 t = __floats2bfloat162_rn(a - ha, b - hb);
    return *reinterpret_cast<uint32_t*>(&t);
}
__device__ __forceinline__ float2 rec2(uint32_t h, uint32_t l) {
    float2 a = __bfloat1622float2(*reinterpret_cast<__nv_bfloat162*>(&h));
    float2 b = __bfloat1622float2(*reinterpret_cast<__nv_bfloat162*>(&l));
    return make_float2(a.x + b.x, a.y + b.y);
}
__device__ __forceinline__ float2 upk(uint32_t h) {
    return __bfloat1622float2(*reinterpret_cast<__nv_bfloat162*>(&h));
}

__global__ __launch_bounds__(256)
void swin_attn_kernel(const float* __restrict__ qkv,
                      const float* __restrict__ mask,
                      const float* __restrict__ rpe,
                      float* __restrict__ out)
{
    extern __shared__ char smc[];
    uint32_t* QHu = (uint32_t*)(smc + QH_B);
    uint32_t* QLu = (uint32_t*)(smc + QL_B);
    uint32_t* KHu = (uint32_t*)(smc + KH_B);
    uint32_t* KLu = (uint32_t*)(smc + KL_B);
    uint32_t* KEu = (uint32_t*)(smc + KEB_B);
    uint32_t* QEu = (uint32_t*)(smc + QEB_B);
    uint32_t* VEu = (uint32_t*)(smc + VEB_B);
    uint32_t* VTHu = (uint32_t*)(smc + VTH_B);
    uint32_t* VTLu = (uint32_t*)(smc + VTL_B);

    const int tid = threadIdx.x, wid = tid >> 5, lane = tid & 31;
    const int h   = blockIdx.y;
    const int b   = blockIdx.x >> 8;
    const int win = blockIdx.x & 255;
    const int wi  = win >> 4, wj = win & 15;

    // ---- load q,k,v; q/k hi-lo bf16 token-major; V^T hi-lo ----
    {
        const int t = tid >> 1, half = tid & 1;
        const int wh = t >> 4, ww = (t >> 1) & 7, n = t & 1;
        const int gy = (wi*8 + wh + SHIFT) & 127;
        const int gx = (wj*8 + ww + SHIFT) & 127;
        const float* base = qkv + (size_t)((((b*128 + gy)*128 + gx)*2 + n)*384) + h*32 + half*16;
        #pragma unroll
        for (int c4 = 0; c4 < 4; c4++) {
            float4 q = ((const float4*)base)[c4];
            float4 k = ((const float4*)(base + 128))[c4];
            float4 v = ((const float4*)(base + 256))[c4];
            q.x *= SCALE; q.y *= SCALE; q.z *= SCALE; q.w *= SCALE;
            const int u = t*20 + half*8 + c4*2;
            QHu[u]   = pkhi(q.x, q.y); QHu[u+1] = pkhi(q.z, q.w);
            QLu[u]   = pklo(q.x, q.y); QLu[u+1] = pklo(q.z, q.w);
            KHu[u]   = pkhi(k.x, k.y); KHu[u+1] = pkhi(k.z, k.w);
            KLu[u]   = pklo(k.x, k.y); KLu[u+1] = pklo(k.z, k.w);
            float vv[4] = {v.x, v.y, v.z, v.w};
            #pragma unroll
            for (int e = 0; e < 4; e++) {
                const int c = half*16 + c4*4 + e;
                __nv_bfloat16 hi = __float2bfloat16(vv[e]);
                __nv_bfloat16 lo = __float2bfloat16(vv[e] - __bfloat162float(hi));
                ((__nv_bfloat16*)VTHu)[c*136 + t] = hi;
                ((__nv_bfloat16*)VTLu)[c*136 + t] = lo;
            }
        }
    }
    // ---- rel-pos tables -> bf16 (head-major row: q|k|v, 32 each) ----
    for (int idx = tid; idx < NR*24; idx += 256) {
        const int r = idx / 24, s = idx % 24;
        const int sl = s >> 3, c4 = s & 7;
        float4 v = *(const float4*)(rpe + (size_t)r*384 + h*96 + sl*32 + c4*4);
        uint32_t* dst = (sl == 0) ? QEu : (sl == 1) ? KEu : VEu;
        if (sl == 0) { v.x *= SCALE; v.y *= SCALE; v.z *= SCALE; v.w *= SCALE; }
        uint2 pk;
        pk.x = pkhi(v.x, v.y); pk.y = pkhi(v.z, v.w);
        *(uint2*)(dst + r*TSU + c4*2) = pk;
    }
    __syncthreads();   // the only full barrier

    const int r0 = wid*16, r = lane >> 2, cq = lane & 3;
    const int i0 = r0 + r;          // row 0 of this thread
    const int i1 = i0 + 8;          // row 1
    const int p0 = i0 >> 1, p1 = i1 >> 1;
    const int ph0 = p0 >> 3, pw0 = p0 & 7;
    const int ph1 = p1 >> 3, pw1 = p1 & 7;

    // ---- logits in fragment registers: acc[nt][4] ----
    float acc[16][4];
    #pragma unroll
    for (int nt = 0; nt < 16; nt++)
        #pragma unroll
        for (int e = 0; e < 4; e++) acc[nt][e] = 0.f;

    #pragma unroll
    for (int kt = 0; kt < 2; kt++) {
        const int ab = i0*20 + kt*8 + cq;
        uint32_t ah0 = QHu[ab], ah1 = QHu[ab+160], ah2 = QHu[ab+4], ah3 = QHu[ab+164];
        uint32_t al0 = QLu[ab], al1 = QLu[ab+160], al2 = QLu[ab+4], al3 = QLu[ab+164];
        #pragma unroll
        for (int nt = 0; nt < 16; nt++) {
            const int bi = (nt*8 + r)*20 + kt*8 + cq;
            uint32_t bh0 = KHu[bi], bh1 = KHu[bi+4];
            uint32_t bl0 = KLu[bi], bl1 = KLu[bi+4];
            mma_bf16(acc[nt], ah0, ah1, ah2, ah3, bh0, bh1);
            mma_bf16(acc[nt], al0, al1, al2, al3, bh0, bh1);
            mma_bf16(acc[nt], ah0, ah1, ah2, ah3, bl0, bl1);
        }
    }
    // mask
    {
        const float* mrow = mask + (size_t)win*16384;
        #pragma unroll
        for (int nt = 0; nt < 16; nt++) {
            const int j0 = nt*8 + cq*2;
            float2 m0 = *(const float2*)(mrow + i0*128 + j0);
            float2 m1 = *(const float2*)(mrow + i1*128 + j0);
            acc[nt][0] += m0.x; acc[nt][1] += m0.y;
            acc[nt][2] += m1.x; acc[nt][3] += m1.y;
        }
    }

    // ---- qr term: q[i] . KE[r(pi,pj)], same value for both cols of the pair ----
    #pragma unroll
    for (int rowv = 0; rowv < 2; rowv++) {
        const int i = rowv ? i1 : i0;
        const int ph = rowv ? ph1 : ph0, pw = rowv ? pw1 : pw0;
        float2 qv[16];
        #pragma unroll
        for (int c2 = 0; c2 < 16; c2++) qv[c2] = rec2(QHu[i*20 + c2], QLu[i*20 + c2]);
        #pragma unroll
        for (int nt = 0; nt < 16; nt++) {
            const int pj = 4*nt + cq;
            const int ridx = (ph - (pj >> 3) + 7)*15 + (pw - (pj & 7) + 7);
            float s = 0.f;
            #pragma unroll
            for (int c2 = 0; c2 < 8; c2++) {
                uint2 e = *(const uint2*)(KEu + ridx*TSU + c2*2);
                float2 f0 = upk(e.x), f1 = upk(e.y);
                s += qv[2*c2].x*f0.x + qv[2*c2].y*f0.y + qv[2*c2+1].x*f1.x + qv[2*c2+1].y*f1.y;
            }
            acc[nt][rowv*2+0] += s;
            acc[nt][rowv*2+1] += s;
        }
    }

    // ---- kr term: k[j] . QE[r(pi,pj)] (per column, per row) ----
    #pragma unroll 2
    for (int nt = 0; nt < 16; nt++) {
        const int j0c = nt*8 + cq*2;
        float2 kv0[16], kv1[16];
        #pragma unroll
        for (int c2 = 0; c2 < 16; c2++) {
            kv0[c2] = rec2(KHu[j0c*20 + c2], KLu[j0c*20 + c2]);
            kv1[c2] = rec2(KHu[(j0c+1)*20 + c2], KLu[(j0c+1)*20 + c2]);
        }
        const int pj = 4*nt + cq;
        const int pjh = pj >> 3, pjw = pj & 7;
        #pragma unroll
        for (int rowv = 0; rowv < 2; rowv++) {
            const int ph = rowv ? ph1 : ph0, pw = rowv ? pw1 : pw0;
            const int ridx = (ph - pjh + 7)*15 + (pw - pjw + 7);
            float s0 = 0.f, s1 = 0.f;
            #pragma unroll
            for (int c2 = 0; c2 < 8; c2++) {
                uint2 e = *(const uint2*)(QEu + ridx*TSU + c2*2);
                float2 f0 = upk(e.x), f1 = upk(e.y);
                s0 += kv0[2*c2].x*f0.x + kv0[2*c2].y*f0.y + kv0[2*c2+1].x*f1.x + kv0[2*c2+1].y*f1.y;
                s1 += kv1[2*c2].x*f0.x + kv1[2*c2].y*f0.y + kv1[2*c2+1].x*f1.x + kv1[2*c2+1].y*f1.y;
            }
            acc[nt][rowv*2+0] += s0;
            acc[nt][rowv*2+1] += s1;
        }
    }

    // ---- softmax in registers (reduce within cq-quad) ----
    #pragma unroll
    for (int rowv = 0; rowv < 2; rowv++) {
        float m = -1e30f;
        #pragma unroll
        for (int nt = 0; nt < 16; nt++)
            m = fmaxf(m, fmaxf(acc[nt][rowv*2], acc[nt][rowv*2+1]));
        m = fmaxf(m, __shfl_xor_sync(~0u, m, 1));
        m = fmaxf(m, __shfl_xor_sync(~0u, m, 2));
        float s = 0.f;
        #pragma unroll
        for (int nt = 0; nt < 16; nt++) {
            acc[nt][rowv*2]   = __expf(acc[nt][rowv*2]   - m);
            acc[nt][rowv*2+1] = __expf(acc[nt][rowv*2+1] - m);
            s += acc[nt][rowv*2] + acc[nt][rowv*2+1];
        }
        s += __shfl_xor_sync(~0u, s, 1);
        s += __shfl_xor_sync(~0u, s, 2);
        const float inv = 1.f / s;
        #pragma unroll
        for (int nt = 0; nt < 16; nt++) {
            acc[nt][rowv*2]   *= inv;
            acc[nt][rowv*2+1] *= inv;
        }
    }

    // ---- AV via mma: A fragments built directly from acc registers ----
    float av[4][4];
    #pragma unroll
    for (int ntv = 0; ntv < 4; ntv++)
        #pragma unroll
        for (int e = 0; e < 4; e++) av[ntv][e] = 0.f;
    #pragma unroll
    for (int kt = 0; kt < 8; kt++) {
        uint32_t ah0 = pkhi(acc[2*kt][0],   acc[2*kt][1]);
        uint32_t ah1 = pkhi(acc[2*kt][2],   acc[2*kt][3]);
        uint32_t ah2 = pkhi(acc[2*kt+1][0], acc[2*kt+1][1]);
        uint32_t ah3 = pkhi(acc[2*kt+1][2], acc[2*kt+1][3]);
        uint32_t al0 = pklo(acc[2*kt][0],   acc[2*kt][1]);
        uint32_t al1 = pklo(acc[2*kt][2],   acc[2*kt][3]);
        uint32_t al2 = pklo(acc[2*kt+1][0], acc[2*kt+1][1]);
        uint32_t al3 = pklo(acc[2*kt+1][2], acc[2*kt+1][3]);
        #pragma unroll
        for (int ntv = 0; ntv < 4; ntv++) {
            const int bi = (ntv*8 + r)*VTS + kt*8 + cq;
            uint32_t bh0 = VTHu[bi], bh1 = VTHu[bi+4];
            uint32_t bl0 = VTLu[bi], bl1 = VTLu[bi+4];
            mma_bf16(av[ntv], ah0, ah1, ah2, ah3, bh0, bh1);
            mma_bf16(av[ntv], al0, al1, al2, al3, bh0, bh1);
            mma_bf16(av[ntv], ah0, ah1, ah2, ah3, bl0, bl1);
        }
    }

    // ---- v_embed term per row: oe[c] = sum_pj (a0+a1) * VE[r(pi,pj)][c]; quad-reduce; add; store ----
    #pragma unroll
    for (int rowv = 0; rowv < 2; rowv++) {
        const int i = rowv ? i1 : i0;
        const int ph = rowv ? ph1 : ph0, pw = rowv ? pw1 : pw0;
        float2 oe[16];
        #pragma unroll
        for (int c2 = 0; c2 < 16; c2++) oe[c2] = make_float2(0.f, 0.f);
        #pragma unroll
        for (int nt = 0; nt < 16; nt++) {
            const int pj = 4*nt + cq;
            const int ridx = (ph - (pj >> 3) + 7)*15 + (pw - (pj & 7) + 7);
            const float s = acc[nt][rowv*2] + acc[nt][rowv*2+1];
            #pragma unroll
            for (int c2 = 0; c2 < 8; c2++) {
                uint2 e = *(const uint2*)(VEu + ridx*TSU + c2*2);
                float2 f0 = upk(e.x), f1 = upk(e.y);
                oe[2*c2].x   += s*f0.x; oe[2*c2].y   += s*f0.y;
                oe[2*c2+1].x += s*f1.x; oe[2*c2+1].y += s*f1.y;
            }
        }
        #pragma unroll
        for (int c2 = 0; c2 < 16; c2++) {
            oe[c2].x += __shfl_xor_sync(~0u, oe[c2].x, 1);
            oe[c2].x += __shfl_xor_sync(~0u, oe[c2].x, 2);
            oe[c2].y += __shfl_xor_sync(~0u, oe[c2].y, 1);
            oe[c2].y += __shfl_xor_sync(~0u, oe[c2].y, 2);
        }
        const int p = i >> 1, n = i & 1;
        const int gy = (wi*8 + (p >> 3) + SHIFT) & 127;
        const int gx = (wj*8 + (p & 7) + SHIFT) & 127;
        float* o = out + (size_t)((((b*128 + gy)*128 + gx)*2 + n)*128) + h*32;
        #pragma unroll
        for (int ntv = 0; ntv < 4; ntv++) {
            const int j = ntv*8 + cq*2;
            float2 rv;
            rv.x = av[ntv][rowv*2+0] + oe[4*ntv+cq].x;
            rv.y = av[ntv][rowv*2+1] + oe[4*ntv+cq].y;
            *(float2*)(o + j) = rv;
        }
    }
}

extern "C" void kernel_launch(void* const* d_in, const int* in_sizes, int n_in,
                              void* d_out, int out_size)
{
    const float* qkv  = (const float*)d_in[0];
    const float* mask = (const float*)d_in[1];
    const float* rpe  = (const float*)d_in[2];
    cudaFuncSetAttribute(swin_attn_kernel,
                         cudaFuncAttributeMaxDynamicSharedMemorySize, SMEM_BYTES);
    dim3 grid(1024, 4);
    swin_attn_kernel<<<grid, 256, SMEM_BYTES>>>(qkv, mask, rpe, (float*)d_out);
}

// round 12
// speedup vs baseline: 1.8772x; 1.8772x over previous
#include <cuda_runtime.h>
#include <cuda_bf16.h>
#include <cstdint>

#define SHIFT 4
#define NR 225
#define AS 132
#define ES 36
#define TS 40
#define SCALE 0.17677669529663687f

#define SA_B   0
#define QEB_B  67584
#define KEB_B  86016
#define VEB_B  104448
#define QH_B   122880
#define QL_B   133120
#define KH_B   143360
#define KL_B   153600
#define VTH_B  163840
#define VTL_B  172544
#define OE_B   181248
#define SMEM_BYTES 199680
#define AH_B   67584
#define AL_B   122880

__device__ __forceinline__ void mma_bf16(float* d, uint32_t a0, uint32_t a1, uint32_t a2, uint32_t a3,
                                         uint32_t b0, uint32_t b1) {
    asm volatile(
        "mma.sync.aligned.m16n8k16.row.col.f32.bf16.bf16.f32 "
        "{%0,%1,%2,%3},{%4,%5,%6,%7},{%8,%9},{%0,%1,%2,%3};"
        : "+f"(d[0]), "+f"(d[1]), "+f"(d[2]), "+f"(d[3])
        : "r"(a0), "r"(a1), "r"(a2), "r"(a3), "r"(b0), "r"(b1));
}
__device__ __forceinline__ uint32_t pkhi(float a, float b) {
    __nv_bfloat162 t = __floats2bfloat162_rn(a, b);
    return *reinterpret_cast<uint32_t*>(&t);
}
__device__ __forceinline__ uint32_t pklo(float a, float b) {
    float ha = __bfloat162float(__float2bfloat16(a));
    float hb = __bfloat162float(__float2bfloat16(b));
    __nv_bfloat162 t = __floats2bfloat162_rn(a - ha, b - hb);
    return *reinterpret_cast<uint32_t*>(&t);
}
__device__ __forceinline__ float2 rec2(uint32_t h, uint32_t l) {
    float2 a = __bfloat1622float2(*reinterpret_cast<__nv_bfloat162*>(&h));
    float2 b = __bfloat1622float2(*reinterpret_cast<__nv_bfloat162*>(&l));
    return make_float2(a.x + b.x, a.y + b.y);
}
__device__ __forceinline__ float2 upk(uint32_t h) {
    return __bfloat1622float2(*reinterpret_cast<__nv_bfloat162*>(&h));
}

__global__ __launch_bounds__(256, 1)
void swin_attn_kernel(const float* __restrict__ qkv,
                      const float* __restrict__ mask,
                      const float* __restrict__ rpe,
                      float* __restrict__ out)
{
    extern __shared__ char smc[];
    float* sA  = (float*)(smc + SA_B);
    __nv_bfloat16* QEb = (__nv_bfloat16*)(smc + QEB_B);
    __nv_bfloat16* KEb = (__nv_bfloat16*)(smc + KEB_B);
    __nv_bfloat16* VEb = (__nv_bfloat16*)(smc + VEB_B);
    float* sOE = (float*)(smc + OE_B);
    uint32_t* QHu = (uint32_t*)(smc + QH_B);
    uint32_t* QLu = (uint32_t*)(smc + QL_B);
    uint32_t* KHu = (uint32_t*)(smc + KH_B);
    uint32_t* KLu = (uint32_t*)(smc + KL_B);
    uint32_t* AHu = (uint32_t*)(smc + AH_B);
    uint32_t* ALu = (uint32_t*)(smc + AL_B);
    uint32_t* VTHu = (uint32_t*)(smc + VTH_B);
    uint32_t* VTLu = (uint32_t*)(smc + VTL_B);

    const int tid = threadIdx.x, wid = tid >> 5, lane = tid & 31;
    const int h   = blockIdx.y;
    const int b   = blockIdx.x >> 8;
    const int win = blockIdx.x & 255;
    const int wi  = win >> 4, wj = win & 15;

    // ---- load q,k,v; emit q/k hi-lo bf16 (token-major) + V^T hi-lo ----
    {
        const int t = tid >> 1, half = tid & 1;
        const int wh = t >> 4, ww = (t >> 1) & 7, n = t & 1;
        const int gy = (wi*8 + wh + SHIFT) & 127;
        const int gx = (wj*8 + ww + SHIFT) & 127;
        const float* base = qkv + (size_t)((((b*128 + gy)*128 + gx)*2 + n)*384) + h*32 + half*16;
        #pragma unroll
        for (int c4 = 0; c4 < 4; c4++) {
            float4 q = ((const float4*)base)[c4];
            float4 k = ((const float4*)(base + 128))[c4];
            float4 v = ((const float4*)(base + 256))[c4];
            q.x *= SCALE; q.y *= SCALE; q.z *= SCALE; q.w *= SCALE;
            const int u = t*20 + half*8 + c4*2;
            QHu[u]   = pkhi(q.x, q.y); QHu[u+1] = pkhi(q.z, q.w);
            QLu[u]   = pklo(q.x, q.y); QLu[u+1] = pklo(q.z, q.w);
            KHu[u]   = pkhi(k.x, k.y); KHu[u+1] = pkhi(k.z, k.w);
            KLu[u]   = pklo(k.x, k.y); KLu[u+1] = pklo(k.z, k.w);
            float vv[4] = {v.x, v.y, v.z, v.w};
            #pragma unroll
            for (int e = 0; e < 4; e++) {
                const int c = half*16 + c4*4 + e;
                __nv_bfloat16 hi = __float2bfloat16(vv[e]);
                __nv_bfloat16 lo = __float2bfloat16(vv[e] - __bfloat162float(hi));
                ((__nv_bfloat16*)VTHu)[c*136 + t] = hi;
                ((__nv_bfloat16*)VTLu)[c*136 + t] = lo;
            }
        }
    }
    // ---- rel-pos tables -> bf16 ----
    for (int idx = tid; idx < NR*24; idx += 256) {
        const int r = idx / 24, s = idx % 24;
        const int sl = s >> 3, c4 = s & 7;
        float4 v = *(const float4*)(rpe + (size_t)r*384 + h*96 + sl*32 + c4*4);
        __nv_bfloat16* dst = (sl == 0) ? QEb : (sl == 1) ? KEb : VEb;
        if (sl == 0) { v.x *= SCALE; v.y *= SCALE; v.z *= SCALE; v.w *= SCALE; }
        uint2 pk;
        pk.x = pkhi(v.x, v.y); pk.y = pkhi(v.z, v.w);
        *(uint2*)(dst + r*TS + c4*4) = pk;
    }
    __syncthreads();

    // ---- pass 1: qk via mma.sync (16-row warp tiles), +mask -> sA ----
    {
        const int r0 = wid*16, r = lane >> 2, cq = lane & 3;
        uint32_t ah[2][4], al[2][4];
        #pragma unroll
        for (int kt = 0; kt < 2; kt++) {
            const int base0 = (r0 + r)*20 + kt*8 + cq;
            const int base1 = (r0 + r + 8)*20 + kt*8 + cq;
            ah[kt][0] = QHu[base0];     ah[kt][1] = QHu[base1];
            ah[kt][2] = QHu[base0 + 4]; ah[kt][3] = QHu[base1 + 4];
            al[kt][0] = QLu[base0];     al[kt][1] = QLu[base1];
            al[kt][2] = QLu[base0 + 4]; al[kt][3] = QLu[base1 + 4];
        }
        const float* mrow = mask + (size_t)win*16384;
        #pragma unroll
        for (int nt = 0; nt < 16; nt++) {
            float d[4] = {0.f, 0.f, 0.f, 0.f};
            #pragma unroll
            for (int kt = 0; kt < 2; kt++) {
                const int bidx = (nt*8 + r)*20 + kt*8 + cq;
                uint32_t bh0 = KHu[bidx], bh1 = KHu[bidx + 4];
                uint32_t bl0 = KLu[bidx], bl1 = KLu[bidx + 4];
                mma_bf16(d, ah[kt][0], ah[kt][1], ah[kt][2], ah[kt][3], bh0, bh1);
                mma_bf16(d, al[kt][0], al[kt][1], al[kt][2], al[kt][3], bh0, bh1);
                mma_bf16(d, ah[kt][0], ah[kt][1], ah[kt][2], ah[kt][3], bl0, bl1);
            }
            const int j0 = nt*8 + cq*2;
            const int i0 = r0 + r, i1 = r0 + r + 8;
            float2 m0 = *(const float2*)(mrow + i0*128 + j0);
            float2 m1 = *(const float2*)(mrow + i1*128 + j0);
            *(float2*)(sA + i0*AS + j0) = make_float2(d[0] + m0.x, d[1] + m0.y);
            *(float2*)(sA + i1*AS + j0) = make_float2(d[2] + m1.x, d[3] + m1.y);
        }
    }
    __syncthreads();

    // ---- pass 2: qr term ----
    {
        const int p = tid >> 2, pj0 = (tid & 3) << 4;
        const int phi = p >> 3, pwi = p & 7, i0 = 2*p;
        float4 q0[8], q1[8];
        #pragma unroll
        for (int c4 = 0; c4 < 8; c4++) {
            float2 xy = rec2(QHu[i0*20 + c4*2],     QLu[i0*20 + c4*2]);
            float2 zw = rec2(QHu[i0*20 + c4*2 + 1], QLu[i0*20 + c4*2 + 1]);
            q0[c4] = make_float4(xy.x, xy.y, zw.x, zw.y);
            xy = rec2(QHu[(i0+1)*20 + c4*2],     QLu[(i0+1)*20 + c4*2]);
            zw = rec2(QHu[(i0+1)*20 + c4*2 + 1], QLu[(i0+1)*20 + c4*2 + 1]);
            q1[c4] = make_float4(xy.x, xy.y, zw.x, zw.y);
        }
        #pragma unroll 4
        for (int pj = pj0; pj < pj0 + 16; pj++) {
            const int r = (phi - (pj >> 3) + 7)*15 + (pwi - (pj & 7) + 7);
            float s0 = 0.f, s1 = 0.f;
            #pragma unroll
            for (int c4 = 0; c4 < 8; c4++) {
                uint2 e = *(const uint2*)(KEb + r*TS + c4*4);
                float2 e01 = upk(e.x), e23 = upk(e.y);
                s0 += q0[c4].x*e01.x + q0[c4].y*e01.y + q0[c4].z*e23.x + q0[c4].w*e23.y;
                s1 += q1[c4].x*e01.x + q1[c4].y*e01.y + q1[c4].z*e23.x + q1[c4].w*e23.y;
            }
            float2* d0 = (float2*)(sA + i0*AS + 2*pj);
            float2* d1 = (float2*)(sA + (i0+1)*AS + 2*pj);
            float2 t0 = *d0, t1 = *d1;
            t0.x += s0; t0.y += s0; *d0 = t0;
            t1.x += s1; t1.y += s1; *d1 = t1;
        }
    }
    __syncthreads();

    // ---- pass 3: kr term ----
    {
        const int p = tid >> 2, pi0 = (tid & 3) << 4;
        const int phj = p >> 3, pwj = p & 7, j0 = 2*p;
        float4 k0[8], k1[8];
        #pragma unroll
        for (int c4 = 0; c4 < 8; c4++) {
            float2 xy = rec2(KHu[j0*20 + c4*2],     KLu[j0*20 + c4*2]);
            float2 zw = rec2(KHu[j0*20 + c4*2 + 1], KLu[j0*20 + c4*2 + 1]);
            k0[c4] = make_float4(xy.x, xy.y, zw.x, zw.y);
            xy = rec2(KHu[(j0+1)*20 + c4*2],     KLu[(j0+1)*20 + c4*2]);
            zw = rec2(KHu[(j0+1)*20 + c4*2 + 1], KLu[(j0+1)*20 + c4*2 + 1]);
            k1[c4] = make_float4(xy.x, xy.y, zw.x, zw.y);
        }
        #pragma unroll 4
        for (int pi = pi0; pi < pi0 + 16; pi++) {
            const int r = ((pi >> 3) - phj + 7)*15 + ((pi & 7) - pwj + 7);
            float s0 = 0.f, s1 = 0.f;
            #pragma unroll
            for (int c4 = 0; c4 < 8; c4++) {
                uint2 e = *(const uint2*)(QEb + r*TS + c4*4);
                float2 e01 = upk(e.x), e23 = upk(e.y);
                s0 += k0[c4].x*e01.x + k0[c4].y*e01.y + k0[c4].z*e23.x + k0[c4].w*e23.y;
                s1 += k1[c4].x*e01.x + k1[c4].y*e01.y + k1[c4].z*e23.x + k1[c4].w*e23.y;
            }
            float2* d0 = (float2*)(sA + (2*pi)*AS + j0);
            float2* d1 = (float2*)(sA + (2*pi+1)*AS + j0);
            float2 t0 = *d0, t1 = *d1;
            t0.x += s0; t0.y += s1; *d0 = t0;
            t1.x += s0; t1.y += s1; *d1 = t1;
        }
    }
    __syncthreads();

    // ---- fused softmax + bf16 emit + pair-sum (in place) ----
    // lane l owns column pairs (2l,2l+1) and (64+2l,64+2l+1) of each row.
    // After normalization: emit AH/AL fragments directly, and store the
    // pair sums into sA[i*AS + pj] (pj = l and 32+l) for the v_embed pass.
    {
        const int w = tid >> 5, l = lane;
        for (int ii = 0; ii < 16; ii++) {
            const int i = w*16 + ii;
            float2 v01 = *(const float2*)(sA + i*AS + 2*l);
            float2 v23 = *(const float2*)(sA + i*AS + 64 + 2*l);
            float m = fmaxf(fmaxf(v01.x, v01.y), fmaxf(v23.x, v23.y));
            #pragma unroll
            for (int off = 16; off; off >>= 1) m = fmaxf(m, __shfl_xor_sync(~0u, m, off));
            float e0 = __expf(v01.x - m), e1 = __expf(v01.y - m);
            float e2 = __expf(v23.x - m), e3 = __expf(v23.y - m);
            float s = e0 + e1 + e2 + e3;
            #pragma unroll
            for (int off = 16; off; off >>= 1) s += __shfl_xor_sync(~0u, s, off);
            const float inv = 1.f / s;
            e0 *= inv; e1 *= inv; e2 *= inv; e3 *= inv;
            AHu[i*68 + l]      = pkhi(e0, e1);
            ALu[i*68 + l]      = pklo(e0, e1);
            AHu[i*68 + 32 + l] = pkhi(e2, e3);
            ALu[i*68 + 32 + l] = pklo(e2, e3);
            sA[i*AS + l]       = e0 + e1;   // pair sum, pj = l
            sA[i*AS + 32 + l]  = e2 + e3;   // pair sum, pj = 32 + l
        }
    }
    __syncthreads();

    // ---- scalar v_embed term (reads pair sums) -> sOE ----
    {
        const int p = tid >> 2, c0 = (tid & 3) << 3;
        const int phi = p >> 3, pwi = p & 7, i0 = 2*p;
        float4 a0a = {0,0,0,0}, a0b = {0,0,0,0}, a1a = {0,0,0,0}, a1b = {0,0,0,0};
        #pragma unroll 4
        for (int pj = 0; pj < 64; pj++) {
            const float s0 = sA[i0*AS + pj];
            const float s1 = sA[(i0+1)*AS + pj];
            const int r = (phi - (pj >> 3) + 7)*15 + (pwi - (pj & 7) + 7);
            uint2 ea = *(const uint2*)(VEb + r*TS + c0);
            uint2 eb = *(const uint2*)(VEb + r*TS + c0 + 4);
            float2 e0 = upk(ea.x), e1 = upk(ea.y), e2 = upk(eb.x), e3 = upk(eb.y);
            a0a.x += s0*e0.x; a0a.y += s0*e0.y; a0a.z += s0*e1.x; a0a.w += s0*e1.y;
            a0b.x += s0*e2.x; a0b.y += s0*e2.y; a0b.z += s0*e3.x; a0b.w += s0*e3.y;
            a1a.x += s1*e0.x; a1a.y += s1*e0.y; a1a.z += s1*e1.x; a1a.w += s1*e1.y;
            a1b.x += s1*e2.x; a1b.y += s1*e2.y; a1b.z += s1*e3.x; a1b.w += s1*e3.y;
        }
        *(float4*)(sOE + i0*ES + c0)         = a0a;
        *(float4*)(sOE + i0*ES + c0 + 4)     = a0b;
        *(float4*)(sOE + (i0+1)*ES + c0)     = a1a;
        *(float4*)(sOE + (i0+1)*ES + c0 + 4) = a1b;
    }
    __syncthreads();

    // ---- AV via mma.sync + add embed partial + store ----
    {
        const int r0 = wid*16, r = lane >> 2, cq = lane & 3;
        float d[4][4];
        #pragma unroll
        for (int nt = 0; nt < 4; nt++)
            #pragma unroll
            for (int e = 0; e < 4; e++) d[nt][e] = 0.f;
        #pragma unroll
        for (int kt = 0; kt < 8; kt++) {
            const int a0i = (r0 + r)*68 + kt*8 + cq;
            const int a1i = (r0 + r + 8)*68 + kt*8 + cq;
            uint32_t ah0 = AHu[a0i], ah1 = AHu[a1i], ah2 = AHu[a0i + 4], ah3 = AHu[a1i + 4];
            uint32_t al0 = ALu[a0i], al1 = ALu[a1i], al2 = ALu[a0i + 4], al3 = ALu[a1i + 4];
            #pragma unroll
            for (int nt = 0; nt < 4; nt++) {
                const int bidx = (nt*8 + r)*68 + kt*8 + cq;
                uint32_t bh0 = VTHu[bidx], bh1 = VTHu[bidx + 4];
                uint32_t bl0 = VTLu[bidx], bl1 = VTLu[bidx + 4];
                mma_bf16(d[nt], ah0, ah1, ah2, ah3, bh0, bh1);
                mma_bf16(d[nt], al0, al1, al2, al3, bh0, bh1);
                mma_bf16(d[nt], ah0, ah1, ah2, ah3, bl0, bl1);
            }
        }
        #pragma unroll
        for (int half = 0; half < 2; half++) {
            const int i = r0 + r + half*8;
            const int p = i >> 1, n = i & 1;
            const int gy = (wi*8 + (p >> 3) + SHIFT) & 127;
            const int gx = (wj*8 + (p & 7) + SHIFT) & 127;
            float* o = out + (size_t)((((b*128 + gy)*128 + gx)*2 + n)*128) + h*32;
            #pragma unroll
            for (int nt = 0; nt < 4; nt++) {
                const int j = nt*8 + cq*2;
                float2 e = *(const float2*)(sOE + i*ES + j);
                float2 rv;
                rv.x = d[nt][half*2 + 0] + e.x;
                rv.y = d[nt][half*2 + 1] + e.y;
                *(float2*)(o + j) = rv;
            }
        }
    }
}

extern "C" void kernel_launch(void* const* d_in, const int* in_sizes, int n_in,
                              void* d_out, int out_size)
{
    const float* qkv  = (const float*)d_in[0];
    const float* mask = (const float*)d_in[1];
    const float* rpe  = (const float*)d_in[2];
    cudaFuncSetAttribute(swin_attn_kernel,
                         cudaFuncAttributeMaxDynamicSharedMemorySize, SMEM_BYTES);
    dim3 grid(1024, 4);
    swin_attn_kernel<<<grid, 256, SMEM_BYTES>>>(qkv, mask, rpe, (float*)d_out);
}